// round 2
// baseline (speedup 1.0000x reference)
#include <cuda_runtime.h>
#include <cuda_fp16.h>
#include <stdint.h>

// ValueQuantizer: per-32-group 4-bit asymmetric quant + pack + f16 scale/zero + dequant.
// Warp-per-row (128 elems): lane -> float4, 8-lane subgroup = one quant group.

__device__ __forceinline__ void quant_core(
    const float4 x, int lane,
    float& scale, float& mnv, float& s, float& z,
    float& i0, float& i1, float& i2, float& i3,
    unsigned& p0, unsigned& p1)
{
    float mn = fminf(fminf(x.x, x.y), fminf(x.z, x.w));
    float mx = fmaxf(fmaxf(x.x, x.y), fmaxf(x.z, x.w));
#pragma unroll
    for (int o = 1; o < 8; o <<= 1) {
        mn = fminf(mn, __shfl_xor_sync(0xffffffffu, mn, o));
        mx = fmaxf(mx, __shfl_xor_sync(0xffffffffu, mx, o));
    }
    scale = fmaxf(__fdiv_rn(mx - mn, 15.0f), 1e-8f);
    mnv   = mn;
    __half hs = __float2half_rn(scale);
    __half hz = __float2half_rn(mn);
    s = __half2float(hs);
    z = __half2float(hz);
    // idx: round-half-even, clamp [0,15]; precise division to match reference exactly
    i0 = fminf(fmaxf(rintf(__fdiv_rn(x.x - mn, scale)), 0.0f), 15.0f);
    i1 = fminf(fmaxf(rintf(__fdiv_rn(x.y - mn, scale)), 0.0f), 15.0f);
    i2 = fminf(fmaxf(rintf(__fdiv_rn(x.z - mn, scale)), 0.0f), 15.0f);
    i3 = fminf(fmaxf(rintf(__fdiv_rn(x.w - mn, scale)), 0.0f), 15.0f);
    unsigned u0 = (unsigned)i0, u1 = (unsigned)i1, u2 = (unsigned)i2, u3 = (unsigned)i3;
    p0 = u0 | (u1 << 4);
    p1 = u2 | (u3 << 4);
}

// Primary path: outputs concatenated as float32: [packed | scales | zeros | v_hat]
__global__ void vq_float_concat(const float* __restrict__ v,
                                float* __restrict__ out,
                                int rows)
{
    int gid  = blockIdx.x * blockDim.x + threadIdx.x;
    int row  = gid >> 5;
    int lane = gid & 31;
    if (row >= rows) return;

    const float4 x = reinterpret_cast<const float4*>(v)[(size_t)row * 32 + lane];

    float scale, mn, s, z, i0, i1, i2, i3;
    unsigned p0, p1;
    quant_core(x, lane, scale, mn, s, z, i0, i1, i2, i3, p0, p1);

    const size_t PACKED_N = (size_t)rows * 64;
    const size_t SC_N     = (size_t)rows * 4;
    float* out_packed = out;
    float* out_scales = out + PACKED_N;
    float* out_zeros  = out + PACKED_N + SC_N;
    float* out_vhat   = out + PACKED_N + 2 * SC_N;

    // packed digits as floats: 2 per lane, coalesced
    reinterpret_cast<float2*>(out_packed + (size_t)row * 64)[lane] =
        make_float2((float)p0, (float)p1);

    if ((lane & 7) == 0) {
        int g = lane >> 3;
        out_scales[(size_t)row * 4 + g] = s;
        out_zeros [(size_t)row * 4 + g] = z;
    }

    // v_hat = idx * f16(scale) + f16(zero), separate mul+add like jnp
    float4 vh;
    vh.x = __fadd_rn(__fmul_rn(i0, s), z);
    vh.y = __fadd_rn(__fmul_rn(i1, s), z);
    vh.z = __fadd_rn(__fmul_rn(i2, s), z);
    vh.w = __fadd_rn(__fmul_rn(i3, s), z);
    reinterpret_cast<float4*>(out_vhat + (size_t)row * 128)[lane] = vh;
}

// Fallback A: output is only v_hat (float32)
__global__ void vq_vhat_only(const float* __restrict__ v,
                             float* __restrict__ out,
                             int rows)
{
    int gid  = blockIdx.x * blockDim.x + threadIdx.x;
    int row  = gid >> 5;
    int lane = gid & 31;
    if (row >= rows) return;

    const float4 x = reinterpret_cast<const float4*>(v)[(size_t)row * 32 + lane];
    float scale, mn, s, z, i0, i1, i2, i3;
    unsigned p0, p1;
    quant_core(x, lane, scale, mn, s, z, i0, i1, i2, i3, p0, p1);

    float4 vh;
    vh.x = __fadd_rn(__fmul_rn(i0, s), z);
    vh.y = __fadd_rn(__fmul_rn(i1, s), z);
    vh.z = __fadd_rn(__fmul_rn(i2, s), z);
    vh.w = __fadd_rn(__fmul_rn(i3, s), z);
    reinterpret_cast<float4*>(out + (size_t)row * 128)[lane] = vh;
}

// Fallback B: native byte concatenation [u8 packed | f16 scales | f16 zeros | f32 v_hat]
__global__ void vq_byte_concat(const float* __restrict__ v,
                               uint8_t* __restrict__ out,
                               int rows)
{
    int gid  = blockIdx.x * blockDim.x + threadIdx.x;
    int row  = gid >> 5;
    int lane = gid & 31;
    if (row >= rows) return;

    const float4 x = reinterpret_cast<const float4*>(v)[(size_t)row * 32 + lane];
    float scale, mn, s, z, i0, i1, i2, i3;
    unsigned p0, p1;
    quant_core(x, lane, scale, mn, s, z, i0, i1, i2, i3, p0, p1);

    const size_t PACKED_B = (size_t)rows * 64;          // u8
    const size_t SC_B     = (size_t)rows * 4 * 2;       // f16
    uint8_t* out_packed = out;
    __half*  out_scales = reinterpret_cast<__half*>(out + PACKED_B);
    __half*  out_zeros  = reinterpret_cast<__half*>(out + PACKED_B + SC_B);
    float*   out_vhat   = reinterpret_cast<float*>(out + PACKED_B + 2 * SC_B);

    uchar2 pb; pb.x = (uint8_t)p0; pb.y = (uint8_t)p1;
    reinterpret_cast<uchar2*>(out_packed + (size_t)row * 64)[lane] = pb;

    if ((lane & 7) == 0) {
        int g = lane >> 3;
        out_scales[(size_t)row * 4 + g] = __float2half_rn(scale);
        out_zeros [(size_t)row * 4 + g] = __float2half_rn(mn);
    }

    float4 vh;
    vh.x = __fadd_rn(__fmul_rn(i0, s), z);
    vh.y = __fadd_rn(__fmul_rn(i1, s), z);
    vh.z = __fadd_rn(__fmul_rn(i2, s), z);
    vh.w = __fadd_rn(__fmul_rn(i3, s), z);
    reinterpret_cast<float4*>(out_vhat + (size_t)row * 128)[lane] = vh;
}

extern "C" void kernel_launch(void* const* d_in, const int* in_sizes, int n_in,
                              void* d_out, int out_size)
{
    const float* v = (const float*)d_in[0];
    const int n    = in_sizes[0];        // total input floats
    const int rows = n / 128;

    const long long threads = (long long)rows * 32;
    const int block = 256;
    const int grid  = (int)((threads + block - 1) / block);

    if (out_size == rows * 200) {
        // float32 concat of (packed, scales, zeros, v_hat)
        vq_float_concat<<<grid, block>>>(v, (float*)d_out, rows);
    } else if (out_size == rows * 128) {
        vq_vhat_only<<<grid, block>>>(v, (float*)d_out, rows);
    } else {
        // assume native byte layout
        vq_byte_concat<<<grid, block>>>(v, (uint8_t*)d_out, rows);
    }
}